// round 8
// baseline (speedup 1.0000x reference)
#include <cuda_runtime.h>
#include <cuda_bf16.h>
#include <cstdint>

// ESN collapsed op: out[bt, r] = (1 - lr) * tanh( sum_i x[bt,i] * w[r,i] )
// B*T = 1,048,576 rows, I = 8, R = 128. Store-stream bound (~537MB out).
// cp.async double-buffered x staging; warp = half row, lane owns (r0, r0+1).
// R7: software-pipelined smem loads (A/B register double-buffer, 1 iter ahead)
// to hide LDS latency; indexed addressing; 4 blocks/SM so nothing spills.

__device__ __forceinline__ unsigned long long pk2(float lo, float hi) {
    unsigned long long r;
    asm("mov.b64 %0, {%1, %2};" : "=l"(r) : "f"(lo), "f"(hi));
    return r;
}
__device__ __forceinline__ void upk2(float& lo, float& hi, unsigned long long v) {
    asm("mov.b64 {%0, %1}, %2;" : "=f"(lo), "=f"(hi) : "l"(v));
}
__device__ __forceinline__ unsigned long long mul2(unsigned long long a, unsigned long long b) {
    unsigned long long r;
    asm("mul.rn.f32x2 %0, %1, %2;" : "=l"(r) : "l"(a), "l"(b));
    return r;
}
__device__ __forceinline__ unsigned long long fma2(unsigned long long a, unsigned long long b,
                                                   unsigned long long c) {
    unsigned long long r;
    asm("fma.rn.f32x2 %0, %1, %2, %3;" : "=l"(r) : "l"(a), "l"(b), "l"(c));
    return r;
}
__device__ __forceinline__ float tanh_ap(float x) {
    float y;
    asm("tanh.approx.f32 %0, %1;" : "=f"(y) : "f"(x));
    return y;
}

#define LDS4(v0, v1, v2, v3, addr)                                             \
    asm volatile("ld.shared.v2.u64 {%0, %1}, [%2];"                            \
                 : "=l"(v0), "=l"(v1) : "r"(addr));                            \
    asm volatile("ld.shared.v2.u64 {%0, %1}, [%2];"                            \
                 : "=l"(v2), "=l"(v3) : "r"((addr) + 16));

static constexpr int TILE = 128;           // rows per stage per block
static constexpr int TILE_F = TILE * 8;    // floats per stage (1024 = 4KB)

__global__ void __launch_bounds__(256, 4) ESN_11390253269642_kernel(
    const float* __restrict__ x,     // [BT, 8]
    const float* __restrict__ w,     // [128, 8]
    const float* __restrict__ lrp,   // [1]
    float* __restrict__ out,         // [BT, 128]
    int bt_total)
{
    // two 4KB stages + 256B pad (absorbs the pipeline's one harmless overfetch)
    __shared__ __align__(16) float xs[2 * TILE_F + 64];

    const int tid  = threadIdx.x;
    const int lane = tid & 31;
    const int wid  = tid >> 5;           // 0..7
    const int half = wid & 1;            // which 64-wide half of the row
    const int wrow = wid >> 1;           // 0..3: row offset within stride-4 groups
    const float s = 1.0f - __ldg(lrp);

    // This lane owns r0 = half*64 + lane*2 and r1 = r0+1.
    unsigned long long w0[4], w1[4];
    {
        const int r0 = half * 64 + lane * 2;
        const float4* p0 = reinterpret_cast<const float4*>(w + r0 * 8);
        float4 a = __ldg(p0), b = __ldg(p0 + 1);
        w0[0] = pk2(a.x, a.y); w0[1] = pk2(a.z, a.w);
        w0[2] = pk2(b.x, b.y); w0[3] = pk2(b.z, b.w);
        const float4* p1 = reinterpret_cast<const float4*>(w + (r0 + 1) * 8);
        a = __ldg(p1); b = __ldg(p1 + 1);
        w1[0] = pk2(a.x, a.y); w1[1] = pk2(a.z, a.w);
        w1[2] = pk2(b.x, b.y); w1[3] = pk2(b.z, b.w);
    }

    const long long total_f = (long long)bt_total * 8;
    const int ntiles = (bt_total + TILE - 1) / TILE;
    const uint32_t sbase = (uint32_t)__cvta_generic_to_shared(xs);

    // compute 2 outputs from one row's packed x, store as float2
    auto cs = [&](unsigned long long xv0, unsigned long long xv1,
                  unsigned long long xv2, unsigned long long xv3, float* dst) {
        unsigned long long acc0 = mul2(w0[0], xv0);
        unsigned long long acc1 = mul2(w1[0], xv0);
        acc0 = fma2(w0[1], xv1, acc0);
        acc1 = fma2(w1[1], xv1, acc1);
        acc0 = fma2(w0[2], xv2, acc0);
        acc1 = fma2(w1[2], xv2, acc1);
        acc0 = fma2(w0[3], xv3, acc0);
        acc1 = fma2(w1[3], xv3, acc1);
        float lo0, hi0, lo1, hi1;
        upk2(lo0, hi0, acc0);
        upk2(lo1, hi1, acc1);
        float2 o;
        o.x = s * tanh_ap(lo0 + hi0);
        o.y = s * tanh_ap(lo1 + hi1);
        __stcs(reinterpret_cast<float2*>(dst), o);
    };

    // cp.async: 256 threads x 16B = 4KB = one full tile (stream through L2)
    auto issue_tile = [&](int tile, int buf) {
        long long off = (long long)tile * TILE_F + tid * 4;
        if (off < total_f) {
            uint32_t dst = sbase + (uint32_t)(buf * TILE_F + tid * 4) * 4u;
            const float* src = x + off;
            asm volatile("cp.async.cg.shared.global [%0], [%1], 16;"
                         :: "r"(dst), "l"(src));
        }
    };

    int tile = blockIdx.x;
    int buf = 0;
    if (tile < ntiles) issue_tile(tile, 0);
    asm volatile("cp.async.commit_group;");

    for (; tile < ntiles; tile += gridDim.x) {
        int next = tile + gridDim.x;
        if (next < ntiles) issue_tile(next, buf ^ 1);
        asm volatile("cp.async.commit_group;");
        asm volatile("cp.async.wait_group 1;");
        __syncthreads();

        const uint32_t xa = sbase + (uint32_t)(buf * TILE_F + wrow * 8) * 4u;
        float* op = out + (size_t)(tile * TILE + wrow) * 128 + half * 64 + lane * 2;

        if (tile * TILE + TILE <= bt_total) {
            // full tile, software-pipelined: load j+1 while computing j
            unsigned long long a0, a1, a2, a3, b0, b1, b2, b3;
            LDS4(a0, a1, a2, a3, xa);                       // j = 0
#pragma unroll 4
            for (int jj = 0; jj < 16; jj++) {
                const uint32_t base = xa + (uint32_t)jj * 256u;
                LDS4(b0, b1, b2, b3, base + 128u);          // j = 2jj+1
                cs(a0, a1, a2, a3, op + (size_t)jj * 1024); // j = 2jj
                LDS4(a0, a1, a2, a3, base + 256u);          // j = 2jj+2 (overfetch->pad at jj=15)
                cs(b0, b1, b2, b3, op + (size_t)jj * 1024 + 512); // j = 2jj+1
            }
        } else {
            const int rowlim = bt_total - tile * TILE;
            for (int j = 0; j < 32; j++) {
                if (wrow + j * 4 >= rowlim) break;
                unsigned long long v0, v1, v2, v3;
                LDS4(v0, v1, v2, v3, xa + (uint32_t)j * 128u);
                cs(v0, v1, v2, v3, op + (size_t)j * 512);
            }
        }
        __syncthreads();
        buf ^= 1;
    }
}

extern "C" void kernel_launch(void* const* d_in, const int* in_sizes, int n_in,
                              void* d_out, int out_size)
{
    const float* x   = (const float*)d_in[0];   // [B, T, I] fp32
    const float* w   = (const float*)d_in[1];   // [R, I] fp32
    // d_in[2] = d, unused (contributes exactly 0 in the reference)
    const float* lr  = (const float*)d_in[3];   // [1] fp32
    float* out = (float*)d_out;

    const int bt_total = in_sizes[0] / 8;       // B*T rows

    int ntiles = (bt_total + TILE - 1) / TILE;
    int blocks = 592;                            // 4 blocks/SM x 148 SMs
    if (blocks > ntiles) blocks = ntiles;
    if (blocks < 1) blocks = 1;
    ESN_11390253269642_kernel<<<blocks, 256>>>(x, w, lr, out, bt_total);
}

// round 9
// speedup vs baseline: 1.3772x; 1.3772x over previous
#include <cuda_runtime.h>
#include <cuda_bf16.h>
#include <cstdint>

// ESN collapsed op: out[bt, r] = (1 - lr) * tanh( sum_i x[bt,i] * w[r,i] )
// B*T = 1,048,576 rows, I = 8, R = 128. Store-stream bound (~537MB out).
// Champion config (R4): cp.async double-buffered x staging, warp = half row,
// lane owns (r0, r0+1), TILE=128, 6 blocks/SM, predicated unroll-4 loop.

__device__ __forceinline__ unsigned long long pk2(float lo, float hi) {
    unsigned long long r;
    asm("mov.b64 %0, {%1, %2};" : "=l"(r) : "f"(lo), "f"(hi));
    return r;
}
__device__ __forceinline__ void upk2(float& lo, float& hi, unsigned long long v) {
    asm("mov.b64 {%0, %1}, %2;" : "=f"(lo), "=f"(hi) : "l"(v));
}
__device__ __forceinline__ unsigned long long mul2(unsigned long long a, unsigned long long b) {
    unsigned long long r;
    asm("mul.rn.f32x2 %0, %1, %2;" : "=l"(r) : "l"(a), "l"(b));
    return r;
}
__device__ __forceinline__ unsigned long long fma2(unsigned long long a, unsigned long long b,
                                                   unsigned long long c) {
    unsigned long long r;
    asm("fma.rn.f32x2 %0, %1, %2, %3;" : "=l"(r) : "l"(a), "l"(b), "l"(c));
    return r;
}
__device__ __forceinline__ float tanh_ap(float x) {
    float y;
    asm("tanh.approx.f32 %0, %1;" : "=f"(y) : "f"(x));
    return y;
}

static constexpr int TILE = 128;           // rows per stage per block
static constexpr int TILE_F = TILE * 8;    // floats per stage (1024 = 4KB)

__global__ void __launch_bounds__(256, 6) ESN_11390253269642_kernel(
    const float* __restrict__ x,     // [BT, 8]
    const float* __restrict__ w,     // [128, 8]
    const float* __restrict__ lrp,   // [1]
    float* __restrict__ out,         // [BT, 128]
    int bt_total)
{
    __shared__ float xs[2][TILE_F];

    const int tid  = threadIdx.x;
    const int lane = tid & 31;
    const int wid  = tid >> 5;           // 0..7
    const int half = wid & 1;            // which 64-wide half of the row
    const int wrow = wid >> 1;           // 0..3: row offset within stride-4 groups
    const float s = 1.0f - __ldg(lrp);

    // This lane owns r0 = half*64 + lane*2 and r1 = r0+1.
    // w rows packed as f32x2 pairs (one-time cost).
    unsigned long long w0[4], w1[4];
    {
        const int r0 = half * 64 + lane * 2;
        const float4* p0 = reinterpret_cast<const float4*>(w + r0 * 8);
        float4 a = __ldg(p0), b = __ldg(p0 + 1);
        w0[0] = pk2(a.x, a.y); w0[1] = pk2(a.z, a.w);
        w0[2] = pk2(b.x, b.y); w0[3] = pk2(b.z, b.w);
        const float4* p1 = reinterpret_cast<const float4*>(w + (r0 + 1) * 8);
        a = __ldg(p1); b = __ldg(p1 + 1);
        w1[0] = pk2(a.x, a.y); w1[1] = pk2(a.z, a.w);
        w1[2] = pk2(b.x, b.y); w1[3] = pk2(b.z, b.w);
    }

    const long long total_f = (long long)bt_total * 8;
    const int ntiles = (bt_total + TILE - 1) / TILE;

    // cp.async: 256 threads x 16B = 4KB = one full tile
    auto issue_tile = [&](int tile, int buf) {
        long long off = (long long)tile * TILE_F + tid * 4;
        if (off < total_f) {
            uint32_t dst = (uint32_t)__cvta_generic_to_shared(&xs[buf][tid * 4]);
            const float* src = x + off;
            asm volatile("cp.async.ca.shared.global [%0], [%1], 16;"
                         :: "r"(dst), "l"(src));
        }
    };

    int tile = blockIdx.x;
    int buf = 0;
    if (tile < ntiles) issue_tile(tile, 0);
    asm volatile("cp.async.commit_group;");

    for (; tile < ntiles; tile += gridDim.x) {
        int next = tile + gridDim.x;
        if (next < ntiles) issue_tile(next, buf ^ 1);
        asm volatile("cp.async.commit_group;");
        asm volatile("cp.async.wait_group 1;");
        __syncthreads();

        const int rowlim = bt_total - tile * TILE;   // rows valid in this tile
        // warp handles rows wrow, wrow+4, ..., wrow+124 (32 units), half 'half'
        uint32_t xaddr = (uint32_t)__cvta_generic_to_shared(&xs[buf][wrow * 8]);
        float* obase = out + (size_t)(tile * TILE + wrow) * 128 + half * 64 + lane * 2;
#pragma unroll 4
        for (int j = 0; j < 32; j++) {
            int rit = wrow + j * 4;
            if (rit >= rowlim) break;
            unsigned long long xv0, xv1, xv2, xv3;
            uint32_t a = xaddr + (uint32_t)(j * 4 * 32);  // 4 rows * 32B per j-step
            asm volatile("ld.shared.v2.u64 {%0, %1}, [%2];"
                         : "=l"(xv0), "=l"(xv1) : "r"(a));
            asm volatile("ld.shared.v2.u64 {%0, %1}, [%2];"
                         : "=l"(xv2), "=l"(xv3) : "r"(a + 16));

            unsigned long long acc0 = mul2(w0[0], xv0);
            unsigned long long acc1 = mul2(w1[0], xv0);
            acc0 = fma2(w0[1], xv1, acc0);
            acc1 = fma2(w1[1], xv1, acc1);
            acc0 = fma2(w0[2], xv2, acc0);
            acc1 = fma2(w1[2], xv2, acc1);
            acc0 = fma2(w0[3], xv3, acc0);
            acc1 = fma2(w1[3], xv3, acc1);

            float lo0, hi0, lo1, hi1;
            upk2(lo0, hi0, acc0);
            upk2(lo1, hi1, acc1);
            float2 o;
            o.x = s * tanh_ap(lo0 + hi0);
            o.y = s * tanh_ap(lo1 + hi1);
            __stcs(reinterpret_cast<float2*>(obase + (size_t)j * 4 * 128), o);
        }
        __syncthreads();
        buf ^= 1;
    }
}

extern "C" void kernel_launch(void* const* d_in, const int* in_sizes, int n_in,
                              void* d_out, int out_size)
{
    const float* x   = (const float*)d_in[0];   // [B, T, I] fp32
    const float* w   = (const float*)d_in[1];   // [R, I] fp32
    // d_in[2] = d, unused (contributes exactly 0 in the reference)
    const float* lr  = (const float*)d_in[3];   // [1] fp32
    float* out = (float*)d_out;

    const int bt_total = in_sizes[0] / 8;       // B*T rows

    int ntiles = (bt_total + TILE - 1) / TILE;
    int blocks = 888;                            // 6 blocks/SM x 148 SMs
    if (blocks > ntiles) blocks = ntiles;
    if (blocks < 1) blocks = 1;
    ESN_11390253269642_kernel<<<blocks, 256>>>(x, w, lr, out, bt_total);
}